// round 5
// baseline (speedup 1.0000x reference)
#include <cuda_runtime.h>
#include <cuda_bf16.h>

// Semi-CRF forward DP (HSCRF). B=16, L=128, T=11, K=7.
// R5 (= R4 resubmit after infra failure): fixed 128-step loop unrolled x8
// (ring indices become compile-time), 96 threads (3 warps), 8-lane segments:
// thread (y, yp2) covers yp2 & yp2+8, 3-shfl yp-reduce, stale-2 scale M,
// depth-2 register score prefetch, log2-domain, in-kernel final reduction.

#define B_ 16
#define L_ 128
#define T_ 11
#define K_ 7
#define TT_ 121
#define NEGBIG  (-1e30f)
#define LOG2E_F 1.4426950408889634f
#define LN2_F   0.6931471805599453f
#define STEP_EL (129 * TT_)   /* elem offset per end-position: 15609 */
#define KOFF_EL (128 * TT_)   /* elem offset per k step: 15488 */

__device__ float g_partial[B_];
__device__ unsigned int g_tickets;   // module-lifetime; one winner per launch

__device__ __forceinline__ float ex2f(float x) {
    float r; asm("ex2.approx.ftz.f32 %0, %1;" : "=f"(r) : "f"(x)); return r;
}
__device__ __forceinline__ float lg2f(float x) {
    float r; asm("lg2.approx.f32 %0, %1;" : "=f"(r) : "f"(x)); return r;
}

__global__ void __launch_bounds__(96, 1) dp_kernel(const float* __restrict__ scores,
                                                   const int* __restrict__ mask,
                                                   float* __restrict__ out) {
    const int b   = blockIdx.x;
    const int tid = threadIdx.x;
    const int y   = tid >> 3;        // 0..11 (y==11 -> idle segment)
    const int l8  = tid & 7;         // lane in segment
    const int ypA = l8;              // first yp handled (0..7, always < T_)
    const int ypB = l8 + 8;          // second yp (valid if < 11, i.e. l8 < 3)
    const bool actY = (y < T_);
    const bool actB = actY && (ypB < T_);

    __shared__ float a_ring[8][16];  // alpha (log2 domain), [slot][label]
    __shared__ float r_ring[8];      // per-slot scale proxy (label 0)

    if (tid < 8) r_ring[tid] = 0.f;
    for (int t = tid; t < 128; t += 96) {
        int s = t >> 4, c = t & 15;
        a_ring[s][c] = (s == 0) ? ((c == T_ - 1) ? 0.f : -10000.f * LOG2E_F) : 0.f;
    }

    const int len = mask[b];  // in [64, 128]
    const size_t boff = (size_t)b * (L_ * L_ * TT_);
    const float* pA = scores + boff + ypA * T_ + y;
    const float* pB = scores + boff + ypB * T_ + y;

    // score buffers: parity p = e&1; sX[p][k] holds step e's scores
    float sA[2][K_], sB[2][K_];
#pragma unroll
    for (int ee = 0; ee < 2; ee++)
#pragma unroll
        for (int k = 0; k < K_; k++) {
            int j = ee - (K_ - 1) + k;
            long off = (long)ee * STEP_EL + (long)(k - 6) * KOFF_EL;
            sA[ee][k] = (actY && j >= 0) ? __ldg(pA + off) : NEGBIG;
            sB[ee][k] = (actB && j >= 0) ? __ldg(pB + off) : NEGBIG;
        }

    // register-carried alpha window: awX[k] <-> alpha[e-6+k][ypX]
    float awA[K_], awB[K_];
#pragma unroll
    for (int k = 0; k < K_; k++) { awA[k] = 0.f; awB[k] = 0.f; }

    float res = 0.f;
    __syncthreads();

    const float* qA = pA + 2 * STEP_EL;   // base for prefetch of step e+2
    const float* qB = pB + 2 * STEP_EL;

#pragma unroll 1
    for (int eb = 0; eb < L_; eb += 8) {
#pragma unroll
        for (int u = 0; u < 8; u++) {
            const int e = eb + u;          // e&7 == u (compile-time slots)
            const int p = u & 1;

            // stale-2 scale: alpha[e-2][0], written two steps ago
            const float M = r_ring[(u + 6) & 7];

            // slide alpha window; newest row written last step to slot u
#pragma unroll
            for (int k = 0; k < K_ - 1; k++) { awA[k] = awA[k + 1]; awB[k] = awB[k + 1]; }
            awA[K_ - 1] = a_ring[u][ypA];
            awB[K_ - 1] = a_ring[u][ypB];

            // prefetch scores for step e+2 into temporaries
            const int en = e + 2;
            const bool okhi = (en < L_);
            float tA[K_], tB[K_];
#pragma unroll
            for (int k = 0; k < K_; k++) {
                const bool ok = okhi && (en - (K_ - 1) + k >= 0);
                const long off = (long)u * STEP_EL + (long)(k - 6) * KOFF_EL;
                tA[k] = (actY && ok) ? __ldg(qA + off) : NEGBIG;
                tB[k] = (actB && ok) ? __ldg(qB + off) : NEGBIG;
            }

            // 14 terms: exp2(score*log2e + alpha - M); masked -> 0
            float c0 = 0.f, c1 = 0.f, c2 = 0.f, c3 = 0.f;
#pragma unroll
            for (int k = 0; k < K_; k++) {
                float vA = ex2f(fmaf(sA[p][k], LOG2E_F, awA[k] - M));
                float vB = ex2f(fmaf(sB[p][k], LOG2E_F, awB[k] - M));
                switch (k & 3) {
                    case 0: c0 += vA; c2 += vB; break;
                    case 1: c1 += vA; c3 += vB; break;
                    case 2: c2 += vA; c0 += vB; break;
                    default: c3 += vA; c1 += vB; break;
                }
            }
            float acc = (c0 + c1) + (c2 + c3);

            // reduce over 11 yp within the 8-lane segment
            acc += __shfl_xor_sync(0xffffffffu, acc, 4, 8);
            acc += __shfl_xor_sync(0xffffffffu, acc, 2, 8);
            acc += __shfl_xor_sync(0xffffffffu, acc, 1, 8);

            // segment leader writes new alpha row to slot (e+1)&7 (disjoint
            // from all 7 slots read this step -> single barrier suffices)
            if (l8 == 0 && actY) {
                float an = M + lg2f(acc);
                a_ring[(u + 1) & 7][y] = an;
                if (y == 0) r_ring[(u + 1) & 7] = an;
                if (y == T_ - 2 && (e + 1) == len) res = an;
            }

            // retire prefetched scores into the parity buffer (renamed regs)
#pragma unroll
            for (int k = 0; k < K_; k++) { sA[p][k] = tA[k]; sB[p][k] = tB[k]; }

            __syncthreads();
        }
        qA += 8 * STEP_EL;
        qB += 8 * STEP_EL;
    }

    if (l8 == 0 && y == T_ - 2) g_partial[b] = res * LN2_F;
    __syncthreads();

    // last-finishing block sums the 16 partials (no separate reduce launch)
    if (tid == 0) {
        __threadfence();
        unsigned old = atomicAdd(&g_tickets, 1u);
        if ((old & (B_ - 1)) == (B_ - 1)) {
            __threadfence();
            float s = 0.f;
#pragma unroll
            for (int bb = 0; bb < B_; bb++)
                s += *((volatile float*)&g_partial[bb]);
            out[0] = s;
        }
    }
}

extern "C" void kernel_launch(void* const* d_in, const int* in_sizes, int n_in,
                              void* d_out, int out_size) {
    const float* scores = (const float*)d_in[0];
    const int*   mask   = (const int*)d_in[1];

    dp_kernel<<<B_, 96>>>(scores, mask, (float*)d_out);
}

// round 6
// speedup vs baseline: 1.5165x; 1.5165x over previous
#include <cuda_runtime.h>
#include <cuda_bf16.h>

// Semi-CRF forward DP (HSCRF). B=16, L=128, T=11, K=7.
// R6: R3 structure (192 thr / 6 warps, 16-wide yp segments, 4-shfl reduce,
// depth-3 score prefetch) + fully unrolled x8 steps (compile-time ring and
// score-buffer indices), stale-2 scale M, peeled first/last step-blocks so the
// steady-state body has no mask ALU, fused in-kernel final reduction.

#define B_ 16
#define L_ 128
#define T_ 11
#define K_ 7
#define TT_ 121
#define NEGBIG  (-1e30f)
#define LOG2E_F 1.4426950408889634f
#define LN2_F   0.6931471805599453f
#define STEP_EL (129 * TT_)   /* elem offset per end-position step: 15609 */
#define KOFF_EL (128 * TT_)   /* elem offset per k: 15488 */

__device__ float g_partial[B_];
__device__ unsigned int g_tickets;   // one winner per launch (16 arrivals)

__device__ __forceinline__ float ex2f(float x) {
    float r; asm("ex2.approx.ftz.f32 %0, %1;" : "=f"(r) : "f"(x)); return r;
}
__device__ __forceinline__ float lg2f(float x) {
    float r; asm("lg2.approx.f32 %0, %1;" : "=f"(r) : "f"(x)); return r;
}

// One DP step. U: compile-time step-in-block (e = eb + U).
// PFMODE 0: first block (compile-time j>=0 masks on prefetch)
//        1: steady state (no masks at all)
//        2: last block (skip prefetch when en >= L_, compile-time)
#define DP_STEP(U, PFMODE)                                                     \
    do {                                                                       \
        const float Mv = r_ring[((U) + 6) & 7]; /* alpha[e-2][0], stale-2 */   \
        _Pragma("unroll")                                                      \
        for (int k = 0; k < K_ - 1; k++) aw[k] = aw[k + 1];                    \
        aw[K_ - 1] = a_ring[(U)][yp];          /* alpha[e][yp], slot e&7=U */  \
        if ((PFMODE) != 2 || (U) < 5) {        /* prefetch scores for e+3 */   \
            _Pragma("unroll")                                                  \
            for (int k = 0; k < K_; k++) {                                     \
                bool ok = act;                                                 \
                if ((PFMODE) == 0) ok = ok && (k >= 3 - (U));                  \
                sb[((U) + 3) & 3][k] =                                         \
                    ok ? __ldg(pe + ((U) + 3) * STEP_EL + (k - 6) * KOFF_EL)   \
                       : NEGBIG;                                               \
            }                                                                  \
        }                                                                      \
        float c0 = 0.f, c1 = 0.f, c2 = 0.f, c3 = 0.f;                          \
        if (act) {                                                             \
            _Pragma("unroll")                                                  \
            for (int k = 0; k < K_; k++) {                                     \
                float t = ex2f(fmaf(sb[(U) & 3][k], LOG2E_F, aw[k] - Mv));     \
                switch (k & 3) {                                               \
                    case 0: c0 += t; break;                                    \
                    case 1: c1 += t; break;                                    \
                    case 2: c2 += t; break;                                    \
                    default: c3 += t; break;                                   \
                }                                                              \
            }                                                                  \
        }                                                                      \
        float acc = (c0 + c1) + (c2 + c3);                                     \
        acc += __shfl_xor_sync(0xffffffffu, acc, 8, 16);                       \
        acc += __shfl_xor_sync(0xffffffffu, acc, 4, 16);                       \
        acc += __shfl_xor_sync(0xffffffffu, acc, 2, 16);                       \
        acc += __shfl_xor_sync(0xffffffffu, acc, 1, 16);                       \
        if (yp == 0 && y < T_) {                                               \
            float an = Mv + lg2f(acc);                                         \
            a_ring[((U) + 1) & 7][y] = an;                                     \
            if (y == 0) r_ring[((U) + 1) & 7] = an;                            \
            if (y == T_ - 2 && (eb + (U) + 1) == len) res = an;                \
        }                                                                      \
        __syncthreads();                                                       \
    } while (0)

__global__ void __launch_bounds__(192, 1)
dp_kernel(const float* __restrict__ scores, const int* __restrict__ mask,
          float* __restrict__ out) {
    const int tid = threadIdx.x;
    const int y   = tid >> 4;      // 0..11 (y==11 -> idle segment)
    const int yp  = tid & 15;      // 0..15 (yp>=11 -> padding lanes)
    const bool act = (y < T_) && (yp < T_);

    __shared__ float a_ring[8][16];  // alpha (log2 domain), [slot][label]
    __shared__ float r_ring[8];      // per-slot scale proxy (label 0)

    if (tid < 8) r_ring[tid] = 0.f;
    if (tid < 128) {
        int s = tid >> 4, c = tid & 15;
        a_ring[s][c] = (s == 0) ? ((c == T_ - 1) ? 0.f : -10000.f * LOG2E_F) : 0.f;
    }

    const int len = mask[blockIdx.x];  // in [64, 128]
    const float* base =
        scores + (size_t)blockIdx.x * (L_ * L_ * TT_) + (yp * T_ + y);

    // score ring sb[e&3][k]; prefill e = 0,1,2 (compile-time j>=0 masks)
    float sb[4][K_];
#pragma unroll
    for (int ee = 0; ee < 3; ee++)
#pragma unroll
        for (int k = 0; k < K_; k++)
            sb[ee][k] = (act && (ee - 6 + k) >= 0)
                            ? __ldg(base + ee * STEP_EL + (k - 6) * KOFF_EL)
                            : NEGBIG;

    // register alpha window: aw[k] <-> alpha[e-6+k][yp] (garbage-masked early)
    float aw[K_];
#pragma unroll
    for (int k = 0; k < K_; k++) aw[k] = 0.f;

    float res = 0.f;
    __syncthreads();

    // ── peeled first block: eb = 0 (prefetch needs j>=0 masks) ──
    {
        const int eb = 0;
        const float* pe = base;
        DP_STEP(0, 0); DP_STEP(1, 0); DP_STEP(2, 0); DP_STEP(3, 0);
        DP_STEP(4, 0); DP_STEP(5, 0); DP_STEP(6, 0); DP_STEP(7, 0);
    }

    // ── steady state: eb = 8 .. 112 (no masks anywhere) ──
    {
        const float* pe = base;
#pragma unroll 1
        for (int eb = 8; eb <= 112; eb += 8) {
            pe += 8 * STEP_EL;
            DP_STEP(0, 1); DP_STEP(1, 1); DP_STEP(2, 1); DP_STEP(3, 1);
            DP_STEP(4, 1); DP_STEP(5, 1); DP_STEP(6, 1); DP_STEP(7, 1);
        }
    }

    // ── peeled last block: eb = 120 (skip prefetch past e=127) ──
    {
        const int eb = 120;
        const float* pe = base + 120 * STEP_EL;
        DP_STEP(0, 2); DP_STEP(1, 2); DP_STEP(2, 2); DP_STEP(3, 2);
        DP_STEP(4, 2); DP_STEP(5, 2); DP_STEP(6, 2); DP_STEP(7, 2);
    }

    if (yp == 0 && y == T_ - 2) g_partial[blockIdx.x] = res * LN2_F;
    __syncthreads();

    // last-finishing block sums the 16 partials (no separate reduce launch)
    if (tid == 0) {
        __threadfence();
        unsigned old = atomicAdd(&g_tickets, 1u);
        if ((old & (B_ - 1)) == (B_ - 1)) {
            __threadfence();
            float s = 0.f;
#pragma unroll
            for (int bb = 0; bb < B_; bb++)
                s += *((volatile float*)&g_partial[bb]);
            out[0] = s;
        }
    }
}

extern "C" void kernel_launch(void* const* d_in, const int* in_sizes, int n_in,
                              void* d_out, int out_size) {
    const float* scores = (const float*)d_in[0];
    const int*   mask   = (const int*)d_in[1];

    dp_kernel<<<B_, 192>>>(scores, mask, (float*)d_out);
}

// round 12
// speedup vs baseline: 1.6826x; 1.1096x over previous
#include <cuda_runtime.h>
#include <cuda_bf16.h>

// Semi-CRF forward DP (HSCRF). B=16, L=128, T=11, K=7.
// R11 = R8 resubmit (two broker-level container failures; source unchanged).
// Software-pipelined step: only the k=6 term (alpha_e, published by the
// previous barrier) is on the post-barrier critical path; k<=5 partial for
// step e+1 is precomputed during step e using aw[k+1] = alpha_{e-6+k}.
// Branch-free masking. 192 thr, x8 unroll (compile-time ring slots),
// depth-3 prefetch, register-carried scale M, in-kernel final reduction.

#define B_ 16
#define L_ 128
#define T_ 11
#define K_ 7
#define TT_ 121
#define NEGBIG  (-1e30f)
#define LOG2E_F 1.4426950408889634f
#define LN2_F   0.6931471805599453f
#define STEP_EL (129 * TT_)   /* elem offset per end-position step: 15609 */
#define KOFF_EL (128 * TT_)   /* elem offset per k: 15488 */

__device__ float g_partial[B_];
__device__ unsigned int g_tickets;   // one winner per launch (16 arrivals)

__device__ __forceinline__ float ex2f(float x) {
    float r; asm("ex2.approx.ftz.f32 %0, %1;" : "=f"(r) : "f"(x)); return r;
}
__device__ __forceinline__ float lg2f(float x) {
    float r; asm("lg2.approx.f32 %0, %1;" : "=f"(r) : "f"(x)); return r;
}

// One DP step at e = eb + U (computes alpha_{e+1}).
// PFMODE 0: first block (compile-time j>=0 masks on prefetch)
//        1: steady state (no masks)
//        2: last block (skip prefetch when e+3 >= L_, compile-time)
#define DP_STEP(U, PFMODE)                                                     \
    do {                                                                       \
        const float Mn = r_ring[((U) + 7) & 7];  /* alpha_{e-1}[0] */          \
        /* ── post-barrier critical path ── */                                 \
        const float anew = a_ring[(U)][yp];      /* alpha_e[yp] */             \
        float t6  = ex2f(fmaf(sb[(U) & 3][6], LOG2E_F, anew - Mcur));          \
        float acc = part + t6;                                                 \
        acc += __shfl_xor_sync(0xffffffffu, acc, 8, 16);                       \
        acc += __shfl_xor_sync(0xffffffffu, acc, 4, 16);                       \
        acc += __shfl_xor_sync(0xffffffffu, acc, 2, 16);                       \
        acc += __shfl_xor_sync(0xffffffffu, acc, 1, 16);                       \
        if (yp == 0) {                                                         \
            float an = Mcur + lg2f(acc);                                       \
            a_ring[((U) + 1) & 7][y] = an;                                     \
            if (y == 0) r_ring[((U) + 1) & 7] = an;                            \
            if (y == T_ - 2 && (eb + (U) + 1) == len) res = an;                \
        }                                                                      \
        /* ── filler: window shift, prefetch e+3, next step's partial ── */    \
        _Pragma("unroll")                                                      \
        for (int k = 0; k < K_ - 1; k++) aw[k] = aw[k + 1];                    \
        aw[K_ - 1] = anew;   /* aw[k] = alpha_{e-6+k} */                       \
        if ((PFMODE) != 2 || (U) < 5) {                                        \
            _Pragma("unroll")                                                  \
            for (int k = 0; k < K_; k++) {                                     \
                bool ok = act;                                                 \
                if ((PFMODE) == 0) ok = ok && (k >= 3 - (U));                  \
                sb[((U) + 3) & 3][k] =                                         \
                    ok ? __ldg(pe + ((U) + 3) * STEP_EL + (k - 6) * KOFF_EL)   \
                       : NEGBIG;                                               \
            }                                                                  \
        }                                                                      \
        {   /* part for step e+1: its k-th term uses alpha_{e-5+k} = aw[k+1] */\
            float p0 = 0.f, p1 = 0.f, p2 = 0.f;                                \
            _Pragma("unroll")                                                  \
            for (int k = 0; k < K_ - 1; k++) {                                 \
                float t = ex2f(fmaf(sb[((U) + 1) & 3][k], LOG2E_F,             \
                                    aw[k + 1] - Mn));                          \
                if (k % 3 == 0) p0 += t; else if (k % 3 == 1) p1 += t;         \
                else p2 += t;                                                  \
            }                                                                  \
            part = (p0 + p1) + p2;                                             \
        }                                                                      \
        Mcur = Mn;                                                             \
        __syncthreads();                                                       \
    } while (0)

__global__ void __launch_bounds__(192, 1)
dp_kernel(const float* __restrict__ scores, const int* __restrict__ mask,
          float* __restrict__ out) {
    const int tid = threadIdx.x;
    const int y   = tid >> 4;      // 0..11 (y==11 -> idle segment)
    const int yp  = tid & 15;      // 0..15 (yp>=11 -> padding lanes)
    const bool act = (y < T_) && (yp < T_);

    __shared__ float a_ring[8][16];  // alpha (log2 domain), [slot][label]
    __shared__ float r_ring[8];      // per-slot scale proxy (label 0)

    if (tid < 8) r_ring[tid] = 0.f;
    if (tid < 128) {
        int s = tid >> 4, c = tid & 15;
        a_ring[s][c] = (s == 0) ? ((c == T_ - 1) ? 0.f : -10000.f * LOG2E_F) : 0.f;
    }

    const int len = mask[blockIdx.x];  // in [64, 128]
    const float* base =
        scores + (size_t)blockIdx.x * (L_ * L_ * TT_) + (yp * T_ + y);

    // score ring sb[e&3][k]; prefill e = 0,1,2 (compile-time j>=0 masks)
    float sb[4][K_];
#pragma unroll
    for (int ee = 0; ee < 3; ee++)
#pragma unroll
        for (int k = 0; k < K_; k++)
            sb[ee][k] = (act && (ee - 6 + k) >= 0)
                            ? __ldg(base + ee * STEP_EL + (k - 6) * KOFF_EL)
                            : NEGBIG;

    // register alpha window: aw[k] <-> alpha[e-6+k][yp] (garbage-masked early)
    float aw[K_];
#pragma unroll
    for (int k = 0; k < K_; k++) aw[k] = 0.f;

    float part = 0.f;   // step 0's k<=5 terms are all j<0 -> 0
    float Mcur = 0.f;   // scale for step 0 (r_ring init value)
    float res  = 0.f;
    __syncthreads();

    // ── peeled first block: eb = 0 ──
    {
        const int eb = 0;
        const float* pe = base;
        DP_STEP(0, 0); DP_STEP(1, 0); DP_STEP(2, 0); DP_STEP(3, 0);
        DP_STEP(4, 0); DP_STEP(5, 0); DP_STEP(6, 0); DP_STEP(7, 0);
    }

    // ── steady state: eb = 8 .. 112 ──
    {
        const float* pe = base;
#pragma unroll 1
        for (int eb = 8; eb <= 112; eb += 8) {
            pe += 8 * STEP_EL;
            DP_STEP(0, 1); DP_STEP(1, 1); DP_STEP(2, 1); DP_STEP(3, 1);
            DP_STEP(4, 1); DP_STEP(5, 1); DP_STEP(6, 1); DP_STEP(7, 1);
        }
    }

    // ── peeled last block: eb = 120 ──
    {
        const int eb = 120;
        const float* pe = base + 120 * STEP_EL;
        DP_STEP(0, 2); DP_STEP(1, 2); DP_STEP(2, 2); DP_STEP(3, 2);
        DP_STEP(4, 2); DP_STEP(5, 2); DP_STEP(6, 2); DP_STEP(7, 2);
    }

    if (yp == 0 && y == T_ - 2) g_partial[blockIdx.x] = res * LN2_F;
    __syncthreads();

    // last-finishing block sums the 16 partials (no separate reduce launch)
    if (tid == 0) {
        __threadfence();
        unsigned old = atomicAdd(&g_tickets, 1u);
        if ((old & (B_ - 1)) == (B_ - 1)) {
            __threadfence();
            float s = 0.f;
#pragma unroll
            for (int bb = 0; bb < B_; bb++)
                s += *((volatile float*)&g_partial[bb]);
            out[0] = s;
        }
    }
}

extern "C" void kernel_launch(void* const* d_in, const int* in_sizes, int n_in,
                              void* d_out, int out_size) {
    const float* scores = (const float*)d_in[0];
    const int*   mask   = (const int*)d_in[1];

    dp_kernel<<<B_, 192>>>(scores, mask, (float*)d_out);
}